// round 6
// baseline (speedup 1.0000x reference)
#include <cuda_runtime.h>
#include <cstdint>

// ---------------------------------------------------------------------------
// SpatialWindowSelfAttention (Swin window MHSA), sm_103a — Round 6
//   0) elementwise cvt.rna.tf32 pre-pass for x, Wqkv, Wp
//   1) TF32 GEMM (cp.async 2-stage, XOR-swizzled smem, pure LDS+MMA mainloop)
//   2) window attention with packed fma.rn.f32x2, emits tf32 bits
//   3) TF32 GEMM -> d_out
// ---------------------------------------------------------------------------

#define C_DIM    256
#define QKV_DIM  768
#define N_HEADS  8
#define HEAD_DIM 32
#define IMG      256
#define TOKENS   (IMG * IMG)
#define WS       64
#define MAX_B    2

__device__ float    g_qkv[MAX_B * TOKENS * QKV_DIM];      // f32 (attention input)
__device__ uint32_t g_y  [MAX_B * TOKENS * C_DIM];        // tf32 bits (proj A)
__device__ uint32_t g_xa [MAX_B * TOKENS * C_DIM];        // tf32 bits of x
__device__ uint32_t g_wq [QKV_DIM * C_DIM];               // tf32 bits of Wqkv
__device__ uint32_t g_wp [C_DIM * C_DIM];                 // tf32 bits of Wp

// ---------------------------------------------------------------------------
__device__ __forceinline__ uint32_t f2tf32(float x) {
    uint32_t r;
    asm("cvt.rna.tf32.f32 %0, %1;" : "=r"(r) : "f"(x));
    return r;
}

__device__ __forceinline__ void mma_tf32(float* d, const uint32_t* a, const uint32_t* b) {
    asm volatile(
        "mma.sync.aligned.m16n8k8.row.col.f32.tf32.tf32.f32 "
        "{%0,%1,%2,%3}, {%4,%5,%6,%7}, {%8,%9}, {%0,%1,%2,%3};\n"
        : "+f"(d[0]), "+f"(d[1]), "+f"(d[2]), "+f"(d[3])
        : "r"(a[0]), "r"(a[1]), "r"(a[2]), "r"(a[3]),
          "r"(b[0]), "r"(b[1]));
}

__device__ __forceinline__ void cp_async16(void* smem_dst, const void* gmem_src) {
    uint32_t s = (uint32_t)__cvta_generic_to_shared(smem_dst);
    asm volatile("cp.async.cg.shared.global [%0], [%1], 16;\n" :: "r"(s), "l"(gmem_src));
}
__device__ __forceinline__ void cp_commit() { asm volatile("cp.async.commit_group;\n"); }
template<int N>
__device__ __forceinline__ void cp_wait() {
    asm volatile("cp.async.wait_group %0;\n" :: "n"(N));
}

// packed fp32x2 helpers (FFMA2 — only reachable via PTX)
__device__ __forceinline__ uint64_t pack2(float lo, float hi) {
    uint64_t r; asm("mov.b64 %0, {%1, %2};" : "=l"(r) : "f"(lo), "f"(hi)); return r;
}
__device__ __forceinline__ void unpack2(uint64_t v, float& lo, float& hi) {
    asm("mov.b64 {%0, %1}, %2;" : "=f"(lo), "=f"(hi) : "l"(v));
}
__device__ __forceinline__ uint64_t fma2(uint64_t a, uint64_t b, uint64_t c) {
    uint64_t d; asm("fma.rn.f32x2 %0, %1, %2, %3;" : "=l"(d) : "l"(a), "l"(b), "l"(c));
    return d;
}

// ---------------------------------------------------------------------------
// elementwise f32 -> tf32 bits (vectorized x4)
// ---------------------------------------------------------------------------
__global__ __launch_bounds__(256)
void cvt_tf32_kernel(const float4* __restrict__ in, uint4* __restrict__ out, int n4)
{
    int i = blockIdx.x * blockDim.x + threadIdx.x;
    if (i < n4) {
        float4 v = in[i];
        uint4 o;
        o.x = f2tf32(v.x); o.y = f2tf32(v.y);
        o.z = f2tf32(v.z); o.w = f2tf32(v.w);
        out[i] = o;
    }
}

// ---------------------------------------------------------------------------
// TF32 GEMM: C[M,N] = A[M,K] @ Bw[N,K]^T + bias[N]; A,Bw are tf32 bits.
// BM=BN=128, BK=32, 256 threads (8 warps: 4 M x 2 N), warp tile 32x64.
// 2-stage cp.async. Smem rows of 32 words with XOR swizzle:
//   word(k, row) = k ^ ((row & 7) << 2)   -> conflict-free frag reads,
//   16B-aligned cp.async stores. 32 KB/stage, 64 KB total -> 2 CTAs/SM.
// ---------------------------------------------------------------------------
#define STAGE_WORDS (2 * 128 * 32)     // A + B per stage = 8192 words

__global__ __launch_bounds__(256, 2)
void tf32_gemm_bias_kernel(const uint32_t* __restrict__ A,
                           const uint32_t* __restrict__ Bw,
                           const float* __restrict__ bias,
                           float* __restrict__ C,
                           int M, int N, int K)
{
    constexpr int BK = 32;
    extern __shared__ uint32_t smem[];

    const int tid  = threadIdx.x;
    const int lane = tid & 31;
    const int wid  = tid >> 5;
    const int wm   = (wid & 3) * 32;
    const int wn   = (wid >> 2) * 64;
    const int m0   = blockIdx.y * 128;
    const int n0   = blockIdx.x * 128;
    const int t    = lane & 3;
    const int g    = lane >> 2;

    float acc[2][8][4];
    #pragma unroll
    for (int i = 0; i < 2; i++)
        #pragma unroll
        for (int j = 0; j < 8; j++)
            #pragma unroll
            for (int r = 0; r < 4; r++) acc[i][j][r] = 0.f;

    const int NT = K / BK;

    auto prefetch = [&](int kt, int s) {
        uint32_t* As = smem + s * STAGE_WORDS;
        uint32_t* Bs = As + 128 * 32;
        const int k0 = kt * BK;
        #pragma unroll
        for (int i = 0; i < 4; i++) {
            int f   = tid + i * 256;
            int row = f >> 3;
            int kc  = (f & 7) * 4;
            int sw  = kc ^ ((row & 7) << 2);
            cp_async16(As + row * 32 + sw, A + (size_t)(m0 + row) * K + k0 + kc);
        }
        #pragma unroll
        for (int i = 0; i < 4; i++) {
            int f   = tid + i * 256;
            int row = f >> 3;
            int kc  = (f & 7) * 4;
            int sw  = kc ^ ((row & 7) << 2);
            cp_async16(Bs + row * 32 + sw, Bw + (size_t)(n0 + row) * K + k0 + kc);
        }
        cp_commit();
    };

    prefetch(0, 0);

    for (int kt = 0; kt < NT; kt++) {
        if (kt + 1 < NT) { prefetch(kt + 1, (kt + 1) & 1); cp_wait<1>(); }
        else             { cp_wait<0>(); }
        __syncthreads();

        const uint32_t* As = smem + (kt & 1) * STAGE_WORDS;
        const uint32_t* Bs = As + 128 * 32;
        const int swz = (g & 7) << 2;     // row&7 == g for all fragment rows

        #pragma unroll
        for (int ks = 0; ks < 4; ks++) {
            const int kb = ks * 8;
            const int kA = (kb + t) ^ swz;
            const int kB = (kb + t + 4) ^ swz;
            uint32_t a[2][4], b[8][2];
            #pragma unroll
            for (int mf = 0; mf < 2; mf++) {
                int r = wm + mf * 16 + g;
                a[mf][0] = As[(r    ) * 32 + kA];
                a[mf][1] = As[(r + 8) * 32 + kA];
                a[mf][2] = As[(r    ) * 32 + kB];
                a[mf][3] = As[(r + 8) * 32 + kB];
            }
            #pragma unroll
            for (int nf = 0; nf < 8; nf++) {
                int n = wn + nf * 8 + g;
                b[nf][0] = Bs[n * 32 + kA];
                b[nf][1] = Bs[n * 32 + kB];
            }
            #pragma unroll
            for (int mf = 0; mf < 2; mf++)
                #pragma unroll
                for (int nf = 0; nf < 8; nf++)
                    mma_tf32(acc[mf][nf], a[mf], b[nf]);
        }
        __syncthreads();
    }

    #pragma unroll
    for (int mf = 0; mf < 2; mf++) {
        int row = m0 + wm + mf * 16 + g;
        #pragma unroll
        for (int nf = 0; nf < 8; nf++) {
            int col = n0 + wn + nf * 8 + 2 * t;
            float bx = bias[col], by = bias[col + 1];
            float2 v0 = make_float2(acc[mf][nf][0] + bx, acc[mf][nf][1] + by);
            float2 v1 = make_float2(acc[mf][nf][2] + bx, acc[mf][nf][3] + by);
            *(float2*)(C + (size_t)row * N + col)       = v0;
            *(float2*)(C + (size_t)(row + 8) * N + col) = v1;
        }
    }
}

// ---------------------------------------------------------------------------
// Window attention: block = (window, head), 64 threads, packed f32x2 FMA.
// Coalesced coop loads; output written as tf32 bits (proj A operand).
// ---------------------------------------------------------------------------
__global__ __launch_bounds__(64)
void win_attn_kernel(const float* __restrict__ bias_table)
{
    __shared__ float Qs[WS][HEAD_DIM];
    __shared__ float Ks[WS][HEAD_DIM];
    __shared__ float Vs[WS][HEAD_DIM];
    __shared__ float bias_s[225];

    const int t    = threadIdx.x;
    const int head = blockIdx.y;
    const int bi   = blockIdx.x >> 10;
    const int wid  = blockIdx.x & 1023;
    const int wy   = wid >> 5, wx = wid & 31;

    #pragma unroll
    for (int i = 0; i < 8; i++) {
        int slot = t + i * 64;
        int j    = slot >> 3;
        int f    = slot & 7;
        int jr = j >> 3, jc = j & 7;
        size_t tok = (size_t)bi * TOKENS + (size_t)(wy * 8 + jr) * IMG + (wx * 8 + jc);
        const float4* base = (const float4*)(g_qkv + tok * QKV_DIM + head * HEAD_DIM);
        *(float4*)&Qs[j][f * 4] = base[f];
        *(float4*)&Ks[j][f * 4] = base[f + C_DIM / 4];
        *(float4*)&Vs[j][f * 4] = base[f + 2 * C_DIM / 4];
    }
    for (int i = t; i < 225; i += 64)
        bias_s[i] = bias_table[i * N_HEADS + head];
    __syncthreads();

    const int r = t >> 3, c = t & 7;

    uint64_t q2[16];
    #pragma unroll
    for (int d2 = 0; d2 < 16; d2++) q2[d2] = *(const uint64_t*)&Qs[t][2 * d2];

    const float scale = 0.17677669529663689f;   // 1/sqrt(32)
    float s[WS];
    #pragma unroll
    for (int k = 0; k < WS; k++) {
        const uint64_t* k2 = (const uint64_t*)Ks[k];
        uint64_t a0 = 0ull, a1 = 0ull;          // (+0,+0)
        #pragma unroll
        for (int d2 = 0; d2 < 16; d2 += 2) {
            a0 = fma2(q2[d2    ], k2[d2    ], a0);
            a1 = fma2(q2[d2 + 1], k2[d2 + 1], a1);
        }
        float l0, h0, l1, h1;
        unpack2(a0, l0, h0); unpack2(a1, l1, h1);
        float dot = (l0 + h0) + (l1 + h1);
        int ki = k >> 3, kj = k & 7;
        s[k] = dot * scale + bias_s[(r - ki + 7) * 15 + (c - kj + 7)];
    }

    float m = -1e30f;
    #pragma unroll
    for (int k = 0; k < WS; k++) m = fmaxf(m, s[k]);
    float sum = 0.f;
    #pragma unroll
    for (int k = 0; k < WS; k++) { s[k] = __expf(s[k] - m); sum += s[k]; }
    const float inv = 1.f / sum;

    uint64_t y2[16];
    #pragma unroll
    for (int d2 = 0; d2 < 16; d2++) y2[d2] = 0ull;
    #pragma unroll
    for (int k = 0; k < WS; k++) {
        uint64_t p2 = pack2(s[k], s[k]);
        const uint64_t* v2 = (const uint64_t*)Vs[k];
        #pragma unroll
        for (int d2 = 0; d2 < 16; d2++) y2[d2] = fma2(p2, v2[d2], y2[d2]);
    }

    // stage tf32-converted output in smem (reuse Qs), coop store
    __syncthreads();
    #pragma unroll
    for (int d2 = 0; d2 < 16; d2++) {
        float lo, hi; unpack2(y2[d2], lo, hi);
        Qs[t][2 * d2    ] = __uint_as_float(f2tf32(lo * inv));
        Qs[t][2 * d2 + 1] = __uint_as_float(f2tf32(hi * inv));
    }
    __syncthreads();

    #pragma unroll
    for (int i = 0; i < 8; i++) {
        int slot = t + i * 64;
        int j    = slot >> 3;
        int f    = slot & 7;
        int jr = j >> 3, jc = j & 7;
        size_t tok = (size_t)bi * TOKENS + (size_t)(wy * 8 + jr) * IMG + (wx * 8 + jc);
        uint4* dst = (uint4*)(g_y + tok * C_DIM + head * HEAD_DIM);
        dst[f] = *(const uint4*)&Qs[j][f * 4];
    }
}

// ---------------------------------------------------------------------------
extern "C" void kernel_launch(void* const* d_in, const int* in_sizes, int n_in,
                              void* d_out, int out_size)
{
    const float *x = nullptr, *wqkv_w = nullptr, *wqkv_b = nullptr;
    const float *wp_w = nullptr, *wp_b = nullptr, *bias_table = nullptr;
    long long x_elems = 0;
    for (int i = 0; i < n_in; i++) {
        long long sz = in_sizes[i];
        if      (sz == 768LL * 256)  wqkv_w = (const float*)d_in[i];
        else if (sz == 768)          wqkv_b = (const float*)d_in[i];
        else if (sz == 256LL * 256)  wp_w   = (const float*)d_in[i];
        else if (sz == 256)          wp_b   = (const float*)d_in[i];
        else if (sz == 225LL * 8)    bias_table = (const float*)d_in[i];
        else if (sz > 1000000)       { x = (const float*)d_in[i]; x_elems = sz; }
    }

    const int B = (int)(x_elems / ((long long)TOKENS * C_DIM));   // = 2
    const int M = B * TOKENS;

    float*    qkv_ptr; cudaGetSymbolAddress((void**)&qkv_ptr, g_qkv);
    uint32_t* y_ptr;   cudaGetSymbolAddress((void**)&y_ptr,   g_y);
    uint32_t* xa_ptr;  cudaGetSymbolAddress((void**)&xa_ptr,  g_xa);
    uint32_t* wq_ptr;  cudaGetSymbolAddress((void**)&wq_ptr,  g_wq);
    uint32_t* wp_ptr;  cudaGetSymbolAddress((void**)&wp_ptr,  g_wp);

    const int smem_bytes = 2 * STAGE_WORDS * (int)sizeof(uint32_t);   // 65536
    static bool attr_set = false;
    if (!attr_set) {
        cudaFuncSetAttribute(tf32_gemm_bias_kernel,
                             cudaFuncAttributeMaxDynamicSharedMemorySize, smem_bytes);
        attr_set = true;
    }

    // 0) pre-convert operands to tf32 bits
    {
        int n4 = M * C_DIM / 4;
        cvt_tf32_kernel<<<(n4 + 255) / 256, 256>>>((const float4*)x, (uint4*)xa_ptr, n4);
        int w4 = QKV_DIM * C_DIM / 4;
        cvt_tf32_kernel<<<(w4 + 255) / 256, 256>>>((const float4*)wqkv_w, (uint4*)wq_ptr, w4);
        int p4 = C_DIM * C_DIM / 4;
        cvt_tf32_kernel<<<(p4 + 255) / 256, 256>>>((const float4*)wp_w, (uint4*)wp_ptr, p4);
    }
    // 1) QKV projection
    {
        dim3 grid(QKV_DIM / 128, M / 128);
        tf32_gemm_bias_kernel<<<grid, 256, smem_bytes>>>(xa_ptr, wq_ptr, wqkv_b, qkv_ptr,
                                                         M, QKV_DIM, C_DIM);
    }
    // 2) window attention
    {
        dim3 grid(B * 1024, N_HEADS);
        win_attn_kernel<<<grid, 64>>>(bias_table);
    }
    // 3) output projection
    {
        dim3 grid(C_DIM / 128, M / 128);
        tf32_gemm_bias_kernel<<<grid, 256, smem_bytes>>>(y_ptr, wp_ptr, wp_b, (float*)d_out,
                                                         M, C_DIM, C_DIM);
    }
}

// round 7
// speedup vs baseline: 1.5052x; 1.5052x over previous
#include <cuda_runtime.h>
#include <cstdint>

// ---------------------------------------------------------------------------
// SpatialWindowSelfAttention (Swin window MHSA), sm_103a — Round 7
//   1) TF32 GEMM, 128 thr / 4 warps, 64x64 warp tile (smem-BW fix)
//   2) window attention, coalesced coop loads/stores (R5, measured best)
//   3) TF32 GEMM -> d_out
// ---------------------------------------------------------------------------

#define C_DIM    256
#define QKV_DIM  768
#define N_HEADS  8
#define HEAD_DIM 32
#define IMG      256
#define TOKENS   (IMG * IMG)
#define WS       64
#define MAX_B    2

__device__ float g_qkv[MAX_B * TOKENS * QKV_DIM];
__device__ float g_y  [MAX_B * TOKENS * C_DIM];

// ---------------------------------------------------------------------------
__device__ __forceinline__ uint32_t f2tf32(float x) {
    uint32_t r;
    asm("cvt.rna.tf32.f32 %0, %1;" : "=r"(r) : "f"(x));
    return r;
}

__device__ __forceinline__ void mma_tf32(float* d, const uint32_t* a, const uint32_t* b) {
    asm volatile(
        "mma.sync.aligned.m16n8k8.row.col.f32.tf32.tf32.f32 "
        "{%0,%1,%2,%3}, {%4,%5,%6,%7}, {%8,%9}, {%0,%1,%2,%3};\n"
        : "+f"(d[0]), "+f"(d[1]), "+f"(d[2]), "+f"(d[3])
        : "r"(a[0]), "r"(a[1]), "r"(a[2]), "r"(a[3]),
          "r"(b[0]), "r"(b[1]));
}

// ---------------------------------------------------------------------------
// TF32 GEMM: C[M,N] = A[M,K] @ Bw[N,K]^T + bias[N]
// BM=BN=128, BK=32. 128 threads = 4 warps (2 x M, 2 x N), warp tile 64x64.
// Smem rows stride 36 (36 % 32 == 4): fragment banks 4g+t -> conflict-free.
// Synchronous staging with cvt.rna.tf32 applied at store (R2-proven).
// ---------------------------------------------------------------------------
#define LDS_S 36

__global__ __launch_bounds__(128, 2)
void tf32_gemm_bias_kernel(const float* __restrict__ A,
                           const float* __restrict__ Bw,
                           const float* __restrict__ bias,
                           float* __restrict__ C,
                           int M, int N, int K)
{
    constexpr int BK = 32;
    __shared__ uint32_t As[128][LDS_S];
    __shared__ uint32_t Bs[128][LDS_S];

    const int tid  = threadIdx.x;
    const int lane = tid & 31;
    const int wid  = tid >> 5;           // 0..3
    const int wm   = (wid & 1) * 64;     // warp m offset
    const int wn   = (wid >> 1) * 64;    // warp n offset
    const int m0   = blockIdx.y * 128;
    const int n0   = blockIdx.x * 128;
    const int t    = lane & 3;
    const int g    = lane >> 2;

    float acc[4][8][4];
    #pragma unroll
    for (int i = 0; i < 4; i++)
        #pragma unroll
        for (int j = 0; j < 8; j++)
            #pragma unroll
            for (int r = 0; r < 4; r++) acc[i][j][r] = 0.f;

    for (int k0 = 0; k0 < K; k0 += BK) {
        // stage A tile: 128 rows x 32 k = 1024 float4, 8 per thread
        #pragma unroll
        for (int i = 0; i < 8; i++) {
            int f   = tid + i * 128;
            int row = f >> 3;
            int kc  = (f & 7) * 4;
            float4 v = *(const float4*)(A + (size_t)(m0 + row) * K + k0 + kc);
            As[row][kc + 0] = f2tf32(v.x);
            As[row][kc + 1] = f2tf32(v.y);
            As[row][kc + 2] = f2tf32(v.z);
            As[row][kc + 3] = f2tf32(v.w);
        }
        // stage B tile
        #pragma unroll
        for (int i = 0; i < 8; i++) {
            int f   = tid + i * 128;
            int row = f >> 3;
            int kc  = (f & 7) * 4;
            float4 v = *(const float4*)(Bw + (size_t)(n0 + row) * K + k0 + kc);
            Bs[row][kc + 0] = f2tf32(v.x);
            Bs[row][kc + 1] = f2tf32(v.y);
            Bs[row][kc + 2] = f2tf32(v.z);
            Bs[row][kc + 3] = f2tf32(v.w);
        }
        __syncthreads();

        #pragma unroll
        for (int ks = 0; ks < 4; ks++) {
            const int kb = ks * 8;
            uint32_t a[4][4], b[8][2];
            #pragma unroll
            for (int mf = 0; mf < 4; mf++) {
                int r = wm + mf * 16 + g;
                a[mf][0] = As[r    ][kb + t];
                a[mf][1] = As[r + 8][kb + t];
                a[mf][2] = As[r    ][kb + t + 4];
                a[mf][3] = As[r + 8][kb + t + 4];
            }
            #pragma unroll
            for (int nf = 0; nf < 8; nf++) {
                int n = wn + nf * 8 + g;
                b[nf][0] = Bs[n][kb + t];
                b[nf][1] = Bs[n][kb + t + 4];
            }
            #pragma unroll
            for (int mf = 0; mf < 4; mf++)
                #pragma unroll
                for (int nf = 0; nf < 8; nf++)
                    mma_tf32(acc[mf][nf], a[mf], b[nf]);
        }
        __syncthreads();
    }

    // epilogue: bias + store
    #pragma unroll
    for (int mf = 0; mf < 4; mf++) {
        int row = m0 + wm + mf * 16 + g;
        #pragma unroll
        for (int nf = 0; nf < 8; nf++) {
            int col = n0 + wn + nf * 8 + 2 * t;
            float bx = bias[col], by = bias[col + 1];
            float2 v0 = make_float2(acc[mf][nf][0] + bx, acc[mf][nf][1] + by);
            float2 v1 = make_float2(acc[mf][nf][2] + bx, acc[mf][nf][3] + by);
            *(float2*)(C + (size_t)row * N + col)       = v0;
            *(float2*)(C + (size_t)(row + 8) * N + col) = v1;
        }
    }
}

// ---------------------------------------------------------------------------
// Window attention: block = (window, head), 64 threads (R5, measured best).
// Cooperative coalesced loads: slot s -> token (s>>3), float4 (s&7).
// ---------------------------------------------------------------------------
__global__ __launch_bounds__(64)
void win_attn_kernel(const float* __restrict__ bias_table)
{
    __shared__ float Qs[WS][HEAD_DIM];
    __shared__ float Ks[WS][HEAD_DIM];
    __shared__ float Vs[WS][HEAD_DIM];
    __shared__ float bias_s[225];

    const int t    = threadIdx.x;
    const int head = blockIdx.y;
    const int bi   = blockIdx.x >> 10;
    const int wid  = blockIdx.x & 1023;
    const int wy   = wid >> 5, wx = wid & 31;

    #pragma unroll
    for (int i = 0; i < 8; i++) {
        int slot = t + i * 64;
        int j    = slot >> 3;
        int f    = slot & 7;
        int jr = j >> 3, jc = j & 7;
        size_t tok = (size_t)bi * TOKENS + (size_t)(wy * 8 + jr) * IMG + (wx * 8 + jc);
        const float4* base = (const float4*)(g_qkv + tok * QKV_DIM + head * HEAD_DIM);
        *(float4*)&Qs[j][f * 4] = base[f];
        *(float4*)&Ks[j][f * 4] = base[f + C_DIM / 4];
        *(float4*)&Vs[j][f * 4] = base[f + 2 * C_DIM / 4];
    }
    for (int i = t; i < 225; i += 64)
        bias_s[i] = bias_table[i * N_HEADS + head];
    __syncthreads();

    const int r = t >> 3, c = t & 7;

    float q[HEAD_DIM];
    #pragma unroll
    for (int d = 0; d < HEAD_DIM; d++) q[d] = Qs[t][d];

    const float scale = 0.17677669529663689f;   // 1/sqrt(32)
    float s[WS];
    #pragma unroll
    for (int k = 0; k < WS; k++) {
        float dot = 0.f;
        #pragma unroll
        for (int d = 0; d < HEAD_DIM; d++) dot += q[d] * Ks[k][d];
        int ki = k >> 3, kj = k & 7;
        s[k] = dot * scale + bias_s[(r - ki + 7) * 15 + (c - kj + 7)];
    }

    float m = -1e30f;
    #pragma unroll
    for (int k = 0; k < WS; k++) m = fmaxf(m, s[k]);
    float sum = 0.f;
    #pragma unroll
    for (int k = 0; k < WS; k++) { s[k] = __expf(s[k] - m); sum += s[k]; }
    const float inv = 1.f / sum;

    float y[HEAD_DIM];
    #pragma unroll
    for (int d = 0; d < HEAD_DIM; d++) y[d] = 0.f;
    #pragma unroll
    for (int k = 0; k < WS; k++) {
        float p = s[k];
        #pragma unroll
        for (int d = 0; d < HEAD_DIM; d++) y[d] += p * Vs[k][d];
    }

    // stage output in smem (reuse Qs), then coalesced cooperative store
    __syncthreads();
    #pragma unroll
    for (int d = 0; d < HEAD_DIM; d++) Qs[t][d] = y[d] * inv;
    __syncthreads();

    #pragma unroll
    for (int i = 0; i < 8; i++) {
        int slot = t + i * 64;
        int j    = slot >> 3;
        int f    = slot & 7;
        int jr = j >> 3, jc = j & 7;
        size_t tok = (size_t)bi * TOKENS + (size_t)(wy * 8 + jr) * IMG + (wx * 8 + jc);
        float4* dst = (float4*)(g_y + tok * C_DIM + head * HEAD_DIM);
        dst[f] = *(const float4*)&Qs[j][f * 4];
    }
}

// ---------------------------------------------------------------------------
extern "C" void kernel_launch(void* const* d_in, const int* in_sizes, int n_in,
                              void* d_out, int out_size)
{
    const float *x = nullptr, *wqkv_w = nullptr, *wqkv_b = nullptr;
    const float *wp_w = nullptr, *wp_b = nullptr, *bias_table = nullptr;
    long long x_elems = 0;
    for (int i = 0; i < n_in; i++) {
        long long sz = in_sizes[i];
        if      (sz == 768LL * 256)  wqkv_w = (const float*)d_in[i];
        else if (sz == 768)          wqkv_b = (const float*)d_in[i];
        else if (sz == 256LL * 256)  wp_w   = (const float*)d_in[i];
        else if (sz == 256)          wp_b   = (const float*)d_in[i];
        else if (sz == 225LL * 8)    bias_table = (const float*)d_in[i];
        else if (sz > 1000000)       { x = (const float*)d_in[i]; x_elems = sz; }
    }

    const int B = (int)(x_elems / ((long long)TOKENS * C_DIM));   // = 2
    const int M = B * TOKENS;

    float* qkv_ptr; cudaGetSymbolAddress((void**)&qkv_ptr, g_qkv);
    float* y_ptr;   cudaGetSymbolAddress((void**)&y_ptr,   g_y);

    // 1) QKV projection
    {
        dim3 grid(QKV_DIM / 128, M / 128);
        tf32_gemm_bias_kernel<<<grid, 128>>>(x, wqkv_w, wqkv_b, qkv_ptr,
                                             M, QKV_DIM, C_DIM);
    }
    // 2) window attention
    {
        dim3 grid(B * 1024, N_HEADS);
        win_attn_kernel<<<grid, 64>>>(bias_table);
    }
    // 3) output projection
    {
        dim3 grid(C_DIM / 128, M / 128);
        tf32_gemm_bias_kernel<<<grid, 128>>>(y_ptr, wp_w, wp_b, (float*)d_out,
                                             M, C_DIM, C_DIM);
    }
}